// round 4
// baseline (speedup 1.0000x reference)
#include <cuda_runtime.h>
#include <cuda_bf16.h>

#define N_NODES 100000
#define N_EDGES 1600000
#define IN_CH   48
#define OUT_CH  64
#define V4_PER_ROW (IN_CH / 4)   // 12 float4 per feature row

// -------- scratch (allocation-free: __device__ globals) --------
__device__ __align__(16) float g_h1[N_NODES * IN_CH];
__device__ __align__(16) float g_h2[N_NODES * IN_CH];
__device__ float g_dinv[N_NODES];
__device__ int   g_deg[N_NODES];
__device__ int   g_off[N_NODES + 1];
__device__ int   g_cur[N_NODES];
__device__ int   g_row[N_EDGES];
__device__ int   g_col[N_EDGES];
__device__ int   g_src[N_EDGES];   // CSR-by-dst: source node per slot
__device__ float g_w[N_EDGES];     // CSR-by-dst: edge norm per slot
__device__ int   g_is64;           // 1 if edge_index is int64, 0 if int32

// -------- -1. sniff edge_index dtype (deterministic, on-device) --------
// int64 little-endian indices < 2^31 have every odd int32 word == 0.
// int32 data has random indices at odd words (all-zero prob ~ 0).
__global__ void k_detect(const int* __restrict__ ei32) {
    if (blockIdx.x == 0 && threadIdx.x == 0) {
        int nz = 0;
        for (int i = 0; i < 128; i++) nz |= ei32[2 * i + 1];
        g_is64 = (nz == 0) ? 1 : 0;
    }
}

// -------- 0. zero degree histogram --------
__global__ void k_zero() {
    int i = blockIdx.x * blockDim.x + threadIdx.x;
    if (i < N_NODES) g_deg[i] = 0;
}

// -------- 1. index decode (+clamp) + degree histogram over dst --------
__global__ void k_deg(const void* __restrict__ eiraw) {
    int e = blockIdx.x * blockDim.x + threadIdx.x;
    if (e >= N_EDGES) return;
    int r, c;
    if (g_is64) {
        const long long* ei = (const long long*)eiraw;
        r = (int)ei[e];
        c = (int)ei[N_EDGES + e];
    } else {
        const int* ei = (const int*)eiraw;
        r = ei[e];
        c = ei[N_EDGES + e];
    }
    // clamp: any layout surprise becomes a visible wrong answer, not a trap
    r = min(max(r, 0), N_NODES - 1);
    c = min(max(c, 0), N_NODES - 1);
    g_row[e] = r;
    g_col[e] = c;
    atomicAdd(&g_deg[c], 1);
}

// -------- 2. deg^{-1/2} --------
__global__ void k_dinv() {
    int i = blockIdx.x * blockDim.x + threadIdx.x;
    if (i >= N_NODES) return;
    int d = g_deg[i];
    g_dinv[i] = (d > 0) ? rsqrtf((float)d) : 0.0f;
}

// -------- 3. exclusive scan of deg -> CSR offsets (single block) --------
__global__ void k_scan() {
    __shared__ int sh[1024];
    __shared__ int s_run;
    int tid = threadIdx.x;
    if (tid == 0) s_run = 0;
    __syncthreads();
    for (int base = 0; base < N_NODES; base += 1024) {
        int i = base + tid;
        int v = (i < N_NODES) ? g_deg[i] : 0;
        sh[tid] = v;
        __syncthreads();
        for (int ofs = 1; ofs < 1024; ofs <<= 1) {
            int t = (tid >= ofs) ? sh[tid - ofs] : 0;
            __syncthreads();
            sh[tid] += t;
            __syncthreads();
        }
        if (i < N_NODES) {
            int excl = s_run + sh[tid] - v;
            g_off[i] = excl;
            g_cur[i] = excl;
        }
        int total = sh[1023];
        __syncthreads();               // all reads of s_run done before update
        if (tid == 0) s_run += total;
        __syncthreads();
    }
    if (tid == 0) g_off[N_NODES] = s_run;
}

// -------- 4. counting-sort edges by destination + per-slot norm --------
__global__ void k_place() {
    int e = blockIdx.x * blockDim.x + threadIdx.x;
    if (e >= N_EDGES) return;
    int r = g_row[e];
    int c = g_col[e];
    int pos = atomicAdd(&g_cur[c], 1);
    g_src[pos] = r;
    g_w[pos] = g_dinv[r] * g_dinv[c];
}

// -------- 5. one propagation step, CSR gather (atomic-free) --------
// 12 consecutive threads per destination node; each owns one float4 channel
// chunk. Accumulate all incoming messages in registers, store once.
// stage 0: src = x (input),  dst = g_h1
// stage 1: src = g_h1,       dst = g_h2
__global__ void k_prop_csr(const float4* __restrict__ xin, int stage) {
    const float4* __restrict__ src =
        (stage == 0) ? xin : (const float4*)g_h1;
    float4* __restrict__ dst =
        (stage == 0) ? (float4*)g_h1 : (float4*)g_h2;

    int t = blockIdx.x * blockDim.x + threadIdx.x;
    int node = t / V4_PER_ROW;
    int lane = t - node * V4_PER_ROW;
    if (node >= N_NODES) return;
    int beg = g_off[node];
    int end = g_off[node + 1];
    float4 acc = make_float4(0.f, 0.f, 0.f, 0.f);
    int k = beg;
    for (; k + 2 <= end; k += 2) {
        int   s0 = g_src[k],     s1 = g_src[k + 1];
        float w0 = g_w[k],       w1 = g_w[k + 1];
        float4 v0 = src[s0 * V4_PER_ROW + lane];
        float4 v1 = src[s1 * V4_PER_ROW + lane];
        acc.x += v0.x * w0 + v1.x * w1;
        acc.y += v0.y * w0 + v1.y * w1;
        acc.z += v0.z * w0 + v1.z * w1;
        acc.w += v0.w * w0 + v1.w * w1;
    }
    if (k < end) {
        int   s0 = g_src[k];
        float w0 = g_w[k];
        float4 v0 = src[s0 * V4_PER_ROW + lane];
        acc.x += v0.x * w0;
        acc.y += v0.y * w0;
        acc.z += v0.z * w0;
        acc.w += v0.w * w0;
    }
    dst[node * V4_PER_ROW + lane] = acc;
}

// -------- 6. dense epilogue: out = g_h2 @ W + b --------
__global__ void k_gemm(const float* __restrict__ W,
                       const float* __restrict__ b,
                       float* __restrict__ out) {
    __shared__ float Ws[IN_CH * OUT_CH];
    __shared__ float bs[OUT_CH];
    for (int i = threadIdx.x; i < IN_CH * OUT_CH; i += blockDim.x) Ws[i] = W[i];
    if (threadIdx.x < OUT_CH) bs[threadIdx.x] = b[threadIdx.x];
    __syncthreads();

    int n = blockIdx.x * blockDim.x + threadIdx.x;
    if (n >= N_NODES) return;

    float acc[OUT_CH];
#pragma unroll
    for (int j = 0; j < OUT_CH; j++) acc[j] = bs[j];

    const float4* hr = reinterpret_cast<const float4*>(g_h2 + (long long)n * IN_CH);
    for (int k4 = 0; k4 < V4_PER_ROW; k4++) {
        float4 xv = hr[k4];
        const float* w0 = &Ws[(k4 * 4 + 0) * OUT_CH];
        const float* w1 = &Ws[(k4 * 4 + 1) * OUT_CH];
        const float* w2 = &Ws[(k4 * 4 + 2) * OUT_CH];
        const float* w3 = &Ws[(k4 * 4 + 3) * OUT_CH];
#pragma unroll
        for (int j = 0; j < OUT_CH; j++) {
            acc[j] = fmaf(xv.x, w0[j], acc[j]);
            acc[j] = fmaf(xv.y, w1[j], acc[j]);
            acc[j] = fmaf(xv.z, w2[j], acc[j]);
            acc[j] = fmaf(xv.w, w3[j], acc[j]);
        }
    }

    float4* o = reinterpret_cast<float4*>(out + (long long)n * OUT_CH);
#pragma unroll
    for (int j = 0; j < OUT_CH / 4; j++)
        o[j] = make_float4(acc[4 * j], acc[4 * j + 1], acc[4 * j + 2], acc[4 * j + 3]);
}

extern "C" void kernel_launch(void* const* d_in, const int* in_sizes, int n_in,
                              void* d_out, int out_size) {
    const float* x  = (const float*)d_in[0];   // [N_NODES, IN_CH]
    const void*  ei = d_in[1];                 // [2, N_EDGES] int32 OR int64
    const float* W  = (const float*)d_in[2];   // [IN_CH, OUT_CH]
    const float* b  = (const float*)d_in[3];   // [OUT_CH]
    float*       out = (float*)d_out;          // [N_NODES, OUT_CH]

    // dtype sniff + CSR build
    k_detect<<<1, 32>>>((const int*)ei);
    k_zero<<<(N_NODES + 255) / 256, 256>>>();
    k_deg<<<(N_EDGES + 255) / 256, 256>>>(ei);
    k_dinv<<<(N_NODES + 255) / 256, 256>>>();
    k_scan<<<1, 1024>>>();
    k_place<<<(N_EDGES + 255) / 256, 256>>>();

    // two propagation steps: h1 = A x ; h2 = A h1
    const int threads = 192;                 // 16 nodes per block * 12 lanes
    const int total = N_NODES * V4_PER_ROW;
    int grid = (total + threads - 1) / threads;
    k_prop_csr<<<grid, threads>>>((const float4*)x, 0);
    k_prop_csr<<<grid, threads>>>((const float4*)x, 1);

    // out = h2 @ W + b
    k_gemm<<<(N_NODES + 127) / 128, 128>>>(W, b, out);
}

// round 5
// speedup vs baseline: 1.9191x; 1.9191x over previous
#include <cuda_runtime.h>
#include <cuda_bf16.h>

#define N_NODES 100000
#define N_EDGES 1600000
#define IN_CH   48
#define OUT_CH  64
#define V4_PER_ROW (IN_CH / 4)   // 12 float4 per feature row
#define NB ((N_NODES + 1023) / 1024)   // 98 scan blocks

// -------- scratch (allocation-free: __device__ globals) --------
__device__ __align__(16) float g_h1[N_NODES * IN_CH];
__device__ __align__(16) float g_h2[N_NODES * IN_CH];
__device__ float g_dinv[N_NODES];
__device__ int   g_deg[N_NODES];
__device__ int   g_off[N_NODES + 1];
__device__ int   g_cur[N_NODES];
__device__ int   g_src[N_EDGES];   // CSR-by-dst: source node per slot
__device__ float g_w[N_EDGES];     // CSR-by-dst: edge norm per slot
__device__ int   g_bsum[128];      // per-block degree sums
__device__ int   g_boff[128];      // exclusive scan of block sums
__device__ int   g_is64;           // 1 if edge_index is int64, 0 if int32

// -------- -1. sniff edge_index dtype (deterministic, on-device) --------
// int64 little-endian indices < 2^31 have every odd int32 word == 0.
__global__ void k_detect(const int* __restrict__ ei32) {
    if (blockIdx.x == 0 && threadIdx.x == 0) {
        int nz = 0;
        for (int i = 0; i < 128; i++) nz |= ei32[2 * i + 1];
        g_is64 = (nz == 0) ? 1 : 0;
    }
}

// -------- 0. zero degree histogram --------
__global__ void k_zero() {
    int i = blockIdx.x * blockDim.x + threadIdx.x;
    if (i < N_NODES) g_deg[i] = 0;
}

// -------- 1. degree histogram over dst (decode col half only) --------
__global__ void k_deg(const void* __restrict__ eiraw) {
    int e = blockIdx.x * blockDim.x + threadIdx.x;
    if (e >= N_EDGES) return;
    int c;
    if (g_is64) c = (int)((const long long*)eiraw)[N_EDGES + e];
    else        c = ((const int*)eiraw)[N_EDGES + e];
    c = min(max(c, 0), N_NODES - 1);
    atomicAdd(&g_deg[c], 1);
}

// -------- 2a. per-block exclusive scan (warp shuffles) + dinv --------
__global__ void k_scan1() {
    __shared__ int warp_sums[32];
    int i = blockIdx.x * 1024 + threadIdx.x;
    int v = (i < N_NODES) ? g_deg[i] : 0;
    if (i < N_NODES) g_dinv[i] = (v > 0) ? rsqrtf((float)v) : 0.0f;

    int lane = threadIdx.x & 31;
    int warp = threadIdx.x >> 5;
    // inclusive warp scan
    int s = v;
#pragma unroll
    for (int o = 1; o < 32; o <<= 1) {
        int t = __shfl_up_sync(0xffffffffu, s, o);
        if (lane >= o) s += t;
    }
    if (lane == 31) warp_sums[warp] = s;
    __syncthreads();
    if (warp == 0) {
        int ws = warp_sums[lane];
#pragma unroll
        for (int o = 1; o < 32; o <<= 1) {
            int t = __shfl_up_sync(0xffffffffu, ws, o);
            if (lane >= o) ws += t;
        }
        warp_sums[lane] = ws;
    }
    __syncthreads();
    int excl = s - v + ((warp > 0) ? warp_sums[warp - 1] : 0);
    if (i < N_NODES) g_off[i] = excl;               // block-local exclusive
    if (threadIdx.x == 1023) g_bsum[blockIdx.x] = excl + v;  // block total
}

// -------- 2b. scan the 98 block sums (single small block) --------
__global__ void k_scan2() {
    __shared__ int sh[128];
    int t = threadIdx.x;
    int v = (t < NB) ? g_bsum[t] : 0;
    sh[t] = v;
    __syncthreads();
    for (int o = 1; o < 128; o <<= 1) {
        int x = (t >= o) ? sh[t - o] : 0;
        __syncthreads();
        sh[t] += x;
        __syncthreads();
    }
    g_boff[t] = sh[t] - v;                 // exclusive
    if (t == 127) g_off[N_NODES] = sh[127];  // grand total
}

// -------- 2c. add block offsets; init cursors --------
__global__ void k_scan3() {
    int i = blockIdx.x * blockDim.x + threadIdx.x;
    if (i >= N_NODES) return;
    int o = g_off[i] + g_boff[i >> 10];
    g_off[i] = o;
    g_cur[i] = o;
}

// -------- 3. counting-sort edges by destination + per-slot norm --------
__global__ void k_place(const void* __restrict__ eiraw) {
    int e = blockIdx.x * blockDim.x + threadIdx.x;
    if (e >= N_EDGES) return;
    int r, c;
    if (g_is64) {
        const long long* ei = (const long long*)eiraw;
        r = (int)ei[e];
        c = (int)ei[N_EDGES + e];
    } else {
        const int* ei = (const int*)eiraw;
        r = ei[e];
        c = ei[N_EDGES + e];
    }
    r = min(max(r, 0), N_NODES - 1);
    c = min(max(c, 0), N_NODES - 1);
    int pos = atomicAdd(&g_cur[c], 1);
    g_src[pos] = r;
    g_w[pos] = g_dinv[r] * g_dinv[c];
}

// -------- 4. one propagation step, CSR gather (atomic-free) --------
// 12 consecutive threads per destination node; each owns one float4 channel
// chunk. Accumulate all incoming messages in registers, store once.
__global__ void k_prop_csr(const float4* __restrict__ xin, int stage) {
    const float4* __restrict__ src =
        (stage == 0) ? xin : (const float4*)g_h1;
    float4* __restrict__ dst =
        (stage == 0) ? (float4*)g_h1 : (float4*)g_h2;

    int t = blockIdx.x * blockDim.x + threadIdx.x;
    int node = t / V4_PER_ROW;
    int lane = t - node * V4_PER_ROW;
    if (node >= N_NODES) return;
    int beg = g_off[node];
    int end = g_off[node + 1];
    float4 acc = make_float4(0.f, 0.f, 0.f, 0.f);
    int k = beg;
    // 4-wide unroll for memory-level parallelism on the random gathers
    for (; k + 4 <= end; k += 4) {
        int   s0 = g_src[k],     s1 = g_src[k + 1];
        int   s2 = g_src[k + 2], s3 = g_src[k + 3];
        float w0 = g_w[k],       w1 = g_w[k + 1];
        float w2 = g_w[k + 2],   w3 = g_w[k + 3];
        float4 v0 = src[s0 * V4_PER_ROW + lane];
        float4 v1 = src[s1 * V4_PER_ROW + lane];
        float4 v2 = src[s2 * V4_PER_ROW + lane];
        float4 v3 = src[s3 * V4_PER_ROW + lane];
        acc.x += v0.x * w0 + v1.x * w1 + v2.x * w2 + v3.x * w3;
        acc.y += v0.y * w0 + v1.y * w1 + v2.y * w2 + v3.y * w3;
        acc.z += v0.z * w0 + v1.z * w1 + v2.z * w2 + v3.z * w3;
        acc.w += v0.w * w0 + v1.w * w1 + v2.w * w2 + v3.w * w3;
    }
    for (; k < end; k++) {
        int   s0 = g_src[k];
        float w0 = g_w[k];
        float4 v0 = src[s0 * V4_PER_ROW + lane];
        acc.x += v0.x * w0;
        acc.y += v0.y * w0;
        acc.z += v0.z * w0;
        acc.w += v0.w * w0;
    }
    dst[node * V4_PER_ROW + lane] = acc;
}

// -------- 5. dense epilogue: out = g_h2 @ W + b --------
__global__ void k_gemm(const float* __restrict__ W,
                       const float* __restrict__ b,
                       float* __restrict__ out) {
    __shared__ float Ws[IN_CH * OUT_CH];
    __shared__ float bs[OUT_CH];
    for (int i = threadIdx.x; i < IN_CH * OUT_CH; i += blockDim.x) Ws[i] = W[i];
    if (threadIdx.x < OUT_CH) bs[threadIdx.x] = b[threadIdx.x];
    __syncthreads();

    int n = blockIdx.x * blockDim.x + threadIdx.x;
    if (n >= N_NODES) return;

    float acc[OUT_CH];
#pragma unroll
    for (int j = 0; j < OUT_CH; j++) acc[j] = bs[j];

    const float4* hr = reinterpret_cast<const float4*>(g_h2 + (long long)n * IN_CH);
    for (int k4 = 0; k4 < V4_PER_ROW; k4++) {
        float4 xv = hr[k4];
        const float* w0 = &Ws[(k4 * 4 + 0) * OUT_CH];
        const float* w1 = &Ws[(k4 * 4 + 1) * OUT_CH];
        const float* w2 = &Ws[(k4 * 4 + 2) * OUT_CH];
        const float* w3 = &Ws[(k4 * 4 + 3) * OUT_CH];
#pragma unroll
        for (int j = 0; j < OUT_CH; j++) {
            acc[j] = fmaf(xv.x, w0[j], acc[j]);
            acc[j] = fmaf(xv.y, w1[j], acc[j]);
            acc[j] = fmaf(xv.z, w2[j], acc[j]);
            acc[j] = fmaf(xv.w, w3[j], acc[j]);
        }
    }

    float4* o = reinterpret_cast<float4*>(out + (long long)n * OUT_CH);
#pragma unroll
    for (int j = 0; j < OUT_CH / 4; j++)
        o[j] = make_float4(acc[4 * j], acc[4 * j + 1], acc[4 * j + 2], acc[4 * j + 3]);
}

extern "C" void kernel_launch(void* const* d_in, const int* in_sizes, int n_in,
                              void* d_out, int out_size) {
    const float* x  = (const float*)d_in[0];   // [N_NODES, IN_CH]
    const void*  ei = d_in[1];                 // [2, N_EDGES] int32 OR int64
    const float* W  = (const float*)d_in[2];   // [IN_CH, OUT_CH]
    const float* b  = (const float*)d_in[3];   // [OUT_CH]
    float*       out = (float*)d_out;          // [N_NODES, OUT_CH]

    // dtype sniff + CSR build (parallel scan)
    k_detect<<<1, 32>>>((const int*)ei);
    k_zero<<<(N_NODES + 255) / 256, 256>>>();
    k_deg<<<(N_EDGES + 255) / 256, 256>>>(ei);
    k_scan1<<<NB, 1024>>>();
    k_scan2<<<1, 128>>>();
    k_scan3<<<(N_NODES + 255) / 256, 256>>>();
    k_place<<<(N_EDGES + 255) / 256, 256>>>(ei);

    // two propagation steps: h1 = A x ; h2 = A h1
    const int threads = 192;                 // 16 nodes per block * 12 lanes
    const int total = N_NODES * V4_PER_ROW;
    int grid = (total + threads - 1) / threads;
    k_prop_csr<<<grid, threads>>>((const float4*)x, 0);
    k_prop_csr<<<grid, threads>>>((const float4*)x, 1);

    // out = h2 @ W + b
    k_gemm<<<(N_NODES + 127) / 128, 128>>>(W, b, out);
}

// round 6
// speedup vs baseline: 2.1216x; 1.1055x over previous
#include <cuda_runtime.h>
#include <cuda_fp16.h>
#include <cuda_bf16.h>

#define N_NODES 100000
#define N_EDGES 1600000
#define IN_CH   48
#define OUT_CH  64
#define V4_PER_ROW (IN_CH / 4)   // 12 chunks of 4 channels per feature row
#define NB ((N_NODES + 1023) / 1024)   // 98 scan blocks

// -------- scratch (allocation-free: __device__ globals) --------
__device__ __align__(16) __half g_h1[N_NODES * IN_CH];   // fp16 intermediate
__device__ __align__(16) float  g_h2[N_NODES * IN_CH];   // fp32 (feeds GEMM)
__device__ float g_dinv[N_NODES];
__device__ int   g_deg[N_NODES];
__device__ int   g_off[N_NODES + 1];
__device__ int   g_cur[N_NODES];
__device__ int   g_src[N_EDGES];   // CSR-by-dst: source node per slot
__device__ int   g_bsum[128];      // per-block degree sums
__device__ int   g_boff[128];      // exclusive scan of block sums
__device__ int   g_is64;           // 1 if edge_index is int64, 0 if int32

// -------- 0. zero degree histogram + dtype sniff --------
// int64 little-endian indices < 2^31 have every odd int32 word == 0.
__global__ void k_zero(const int* __restrict__ ei32) {
    int i = blockIdx.x * blockDim.x + threadIdx.x;
    if (i < N_NODES) g_deg[i] = 0;
    if (i == 0) {
        int nz = 0;
        for (int k = 0; k < 128; k++) nz |= ei32[2 * k + 1];
        g_is64 = (nz == 0) ? 1 : 0;
    }
}

// -------- 1. degree histogram over dst (decode col half only) --------
__global__ void k_deg(const void* __restrict__ eiraw) {
    int e = blockIdx.x * blockDim.x + threadIdx.x;
    if (e >= N_EDGES) return;
    int c;
    if (g_is64) c = (int)((const long long*)eiraw)[N_EDGES + e];
    else        c = ((const int*)eiraw)[N_EDGES + e];
    c = min(max(c, 0), N_NODES - 1);
    atomicAdd(&g_deg[c], 1);
}

// -------- 2a. per-block exclusive scan (warp shuffles) + dinv --------
__global__ void k_scan1() {
    __shared__ int warp_sums[32];
    int i = blockIdx.x * 1024 + threadIdx.x;
    int v = (i < N_NODES) ? g_deg[i] : 0;
    if (i < N_NODES) g_dinv[i] = (v > 0) ? rsqrtf((float)v) : 0.0f;

    int lane = threadIdx.x & 31;
    int warp = threadIdx.x >> 5;
    int s = v;
#pragma unroll
    for (int o = 1; o < 32; o <<= 1) {
        int t = __shfl_up_sync(0xffffffffu, s, o);
        if (lane >= o) s += t;
    }
    if (lane == 31) warp_sums[warp] = s;
    __syncthreads();
    if (warp == 0) {
        int ws = warp_sums[lane];
#pragma unroll
        for (int o = 1; o < 32; o <<= 1) {
            int t = __shfl_up_sync(0xffffffffu, ws, o);
            if (lane >= o) ws += t;
        }
        warp_sums[lane] = ws;
    }
    __syncthreads();
    int excl = s - v + ((warp > 0) ? warp_sums[warp - 1] : 0);
    if (i < N_NODES) g_off[i] = excl;                        // block-local excl
    if (threadIdx.x == 1023) g_bsum[blockIdx.x] = excl + v;  // block total
}

// -------- 2b. scan the 98 block sums (single small block) --------
__global__ void k_scan2() {
    __shared__ int sh[128];
    int t = threadIdx.x;
    int v = (t < NB) ? g_bsum[t] : 0;
    sh[t] = v;
    __syncthreads();
    for (int o = 1; o < 128; o <<= 1) {
        int x = (t >= o) ? sh[t - o] : 0;
        __syncthreads();
        sh[t] += x;
        __syncthreads();
    }
    g_boff[t] = sh[t] - v;
    if (t == 127) g_off[N_NODES] = sh[127];
}

// -------- 2c. add block offsets; init cursors --------
__global__ void k_scan3() {
    int i = blockIdx.x * blockDim.x + threadIdx.x;
    if (i >= N_NODES) return;
    int o = g_off[i] + g_boff[i >> 10];
    g_off[i] = o;
    g_cur[i] = o;
}

// -------- 3. counting-sort edges by destination (src only) --------
__global__ void k_place(const void* __restrict__ eiraw) {
    int e = blockIdx.x * blockDim.x + threadIdx.x;
    if (e >= N_EDGES) return;
    int r, c;
    if (g_is64) {
        const long long* ei = (const long long*)eiraw;
        r = (int)ei[e];
        c = (int)ei[N_EDGES + e];
    } else {
        const int* ei = (const int*)eiraw;
        r = ei[e];
        c = ei[N_EDGES + e];
    }
    r = min(max(r, 0), N_NODES - 1);
    c = min(max(c, 0), N_NODES - 1);
    int pos = atomicAdd(&g_cur[c], 1);
    g_src[pos] = r;
}

// -------- 4a. prop step 1: h1(fp16) = A x(fp32) --------
// 12 consecutive threads per destination node; each owns 4 channels.
// Edge norm computed on the fly from g_dinv (L2-hot, broadcast loads).
__global__ void k_prop1(const float4* __restrict__ src) {
    int t = blockIdx.x * blockDim.x + threadIdx.x;
    int node = t / V4_PER_ROW;
    int lane = t - node * V4_PER_ROW;
    if (node >= N_NODES) return;
    int beg = g_off[node];
    int end = g_off[node + 1];
    float dc = g_dinv[node];
    float4 acc = make_float4(0.f, 0.f, 0.f, 0.f);
    int k = beg;
    for (; k + 4 <= end; k += 4) {
        int s0 = g_src[k], s1 = g_src[k + 1], s2 = g_src[k + 2], s3 = g_src[k + 3];
        float w0 = g_dinv[s0] * dc, w1 = g_dinv[s1] * dc;
        float w2 = g_dinv[s2] * dc, w3 = g_dinv[s3] * dc;
        float4 v0 = src[s0 * V4_PER_ROW + lane];
        float4 v1 = src[s1 * V4_PER_ROW + lane];
        float4 v2 = src[s2 * V4_PER_ROW + lane];
        float4 v3 = src[s3 * V4_PER_ROW + lane];
        acc.x += v0.x * w0 + v1.x * w1 + v2.x * w2 + v3.x * w3;
        acc.y += v0.y * w0 + v1.y * w1 + v2.y * w2 + v3.y * w3;
        acc.z += v0.z * w0 + v1.z * w1 + v2.z * w2 + v3.z * w3;
        acc.w += v0.w * w0 + v1.w * w1 + v2.w * w2 + v3.w * w3;
    }
    for (; k < end; k++) {
        int s0 = g_src[k];
        float w0 = g_dinv[s0] * dc;
        float4 v0 = src[s0 * V4_PER_ROW + lane];
        acc.x += v0.x * w0;
        acc.y += v0.y * w0;
        acc.z += v0.z * w0;
        acc.w += v0.w * w0;
    }
    // store 4 channels as fp16 (one 8B store)
    __half2 p0 = __floats2half2_rn(acc.x, acc.y);
    __half2 p1 = __floats2half2_rn(acc.z, acc.w);
    uint2 pk;
    pk.x = *reinterpret_cast<unsigned int*>(&p0);
    pk.y = *reinterpret_cast<unsigned int*>(&p1);
    reinterpret_cast<uint2*>(g_h1)[node * V4_PER_ROW + lane] = pk;
}

// -------- 4b. prop step 2: h2(fp32) = A h1(fp16) --------
__global__ void k_prop2() {
    const uint2* __restrict__ src = reinterpret_cast<const uint2*>(g_h1);
    int t = blockIdx.x * blockDim.x + threadIdx.x;
    int node = t / V4_PER_ROW;
    int lane = t - node * V4_PER_ROW;
    if (node >= N_NODES) return;
    int beg = g_off[node];
    int end = g_off[node + 1];
    float dc = g_dinv[node];
    float4 acc = make_float4(0.f, 0.f, 0.f, 0.f);
    int k = beg;
    for (; k + 4 <= end; k += 4) {
        int s0 = g_src[k], s1 = g_src[k + 1], s2 = g_src[k + 2], s3 = g_src[k + 3];
        float w0 = g_dinv[s0] * dc, w1 = g_dinv[s1] * dc;
        float w2 = g_dinv[s2] * dc, w3 = g_dinv[s3] * dc;
        uint2 r0 = src[s0 * V4_PER_ROW + lane];
        uint2 r1 = src[s1 * V4_PER_ROW + lane];
        uint2 r2 = src[s2 * V4_PER_ROW + lane];
        uint2 r3 = src[s3 * V4_PER_ROW + lane];
        float2 a0 = __half22float2(*reinterpret_cast<__half2*>(&r0.x));
        float2 b0 = __half22float2(*reinterpret_cast<__half2*>(&r0.y));
        float2 a1 = __half22float2(*reinterpret_cast<__half2*>(&r1.x));
        float2 b1 = __half22float2(*reinterpret_cast<__half2*>(&r1.y));
        float2 a2 = __half22float2(*reinterpret_cast<__half2*>(&r2.x));
        float2 b2 = __half22float2(*reinterpret_cast<__half2*>(&r2.y));
        float2 a3 = __half22float2(*reinterpret_cast<__half2*>(&r3.x));
        float2 b3 = __half22float2(*reinterpret_cast<__half2*>(&r3.y));
        acc.x += a0.x * w0 + a1.x * w1 + a2.x * w2 + a3.x * w3;
        acc.y += a0.y * w0 + a1.y * w1 + a2.y * w2 + a3.y * w3;
        acc.z += b0.x * w0 + b1.x * w1 + b2.x * w2 + b3.x * w3;
        acc.w += b0.y * w0 + b1.y * w1 + b2.y * w2 + b3.y * w3;
    }
    for (; k < end; k++) {
        int s0 = g_src[k];
        float w0 = g_dinv[s0] * dc;
        uint2 r0 = src[s0 * V4_PER_ROW + lane];
        float2 a0 = __half22float2(*reinterpret_cast<__half2*>(&r0.x));
        float2 b0 = __half22float2(*reinterpret_cast<__half2*>(&r0.y));
        acc.x += a0.x * w0;
        acc.y += a0.y * w0;
        acc.z += b0.x * w0;
        acc.w += b0.y * w0;
    }
    reinterpret_cast<float4*>(g_h2)[node * V4_PER_ROW + lane] = acc;
}

// -------- 5. dense epilogue: out = g_h2 @ W + b --------
__global__ void k_gemm(const float* __restrict__ W,
                       const float* __restrict__ b,
                       float* __restrict__ out) {
    __shared__ float Ws[IN_CH * OUT_CH];
    __shared__ float bs[OUT_CH];
    for (int i = threadIdx.x; i < IN_CH * OUT_CH; i += blockDim.x) Ws[i] = W[i];
    if (threadIdx.x < OUT_CH) bs[threadIdx.x] = b[threadIdx.x];
    __syncthreads();

    int n = blockIdx.x * blockDim.x + threadIdx.x;
    if (n >= N_NODES) return;

    float acc[OUT_CH];
#pragma unroll
    for (int j = 0; j < OUT_CH; j++) acc[j] = bs[j];

    const float4* hr = reinterpret_cast<const float4*>(g_h2 + (long long)n * IN_CH);
    for (int k4 = 0; k4 < V4_PER_ROW; k4++) {
        float4 xv = hr[k4];
        const float* w0 = &Ws[(k4 * 4 + 0) * OUT_CH];
        const float* w1 = &Ws[(k4 * 4 + 1) * OUT_CH];
        const float* w2 = &Ws[(k4 * 4 + 2) * OUT_CH];
        const float* w3 = &Ws[(k4 * 4 + 3) * OUT_CH];
#pragma unroll
        for (int j = 0; j < OUT_CH; j++) {
            acc[j] = fmaf(xv.x, w0[j], acc[j]);
            acc[j] = fmaf(xv.y, w1[j], acc[j]);
            acc[j] = fmaf(xv.z, w2[j], acc[j]);
            acc[j] = fmaf(xv.w, w3[j], acc[j]);
        }
    }

    float4* o = reinterpret_cast<float4*>(out + (long long)n * OUT_CH);
#pragma unroll
    for (int j = 0; j < OUT_CH / 4; j++)
        o[j] = make_float4(acc[4 * j], acc[4 * j + 1], acc[4 * j + 2], acc[4 * j + 3]);
}

extern "C" void kernel_launch(void* const* d_in, const int* in_sizes, int n_in,
                              void* d_out, int out_size) {
    const float* x  = (const float*)d_in[0];   // [N_NODES, IN_CH]
    const void*  ei = d_in[1];                 // [2, N_EDGES] int32 OR int64
    const float* W  = (const float*)d_in[2];   // [IN_CH, OUT_CH]
    const float* b  = (const float*)d_in[3];   // [OUT_CH]
    float*       out = (float*)d_out;          // [N_NODES, OUT_CH]

    // CSR build (dtype sniff fused into k_zero)
    k_zero<<<(N_NODES + 255) / 256, 256>>>((const int*)ei);
    k_deg<<<(N_EDGES + 255) / 256, 256>>>(ei);
    k_scan1<<<NB, 1024>>>();
    k_scan2<<<1, 128>>>();
    k_scan3<<<(N_NODES + 255) / 256, 256>>>();
    k_place<<<(N_EDGES + 255) / 256, 256>>>(ei);

    // two propagation steps: h1 = A x ; h2 = A h1
    const int threads = 192;                 // 16 nodes per block * 12 lanes
    const int total = N_NODES * V4_PER_ROW;
    int grid = (total + threads - 1) / threads;
    k_prop1<<<grid, threads>>>((const float4*)x);
    k_prop2<<<grid, threads>>>();

    // out = h2 @ W + b
    k_gemm<<<(N_NODES + 127) / 128, 128>>>(W, b, out);
}

// round 9
// speedup vs baseline: 2.1772x; 1.0262x over previous
#include <cuda_runtime.h>
#include <cuda_fp16.h>
#include <cuda_bf16.h>

#define N_NODES 100000
#define N_EDGES 1600000
#define IN_CH   48
#define OUT_CH  64
#define V4_PER_ROW (IN_CH / 4)   // 12 chunks of 4 channels per feature row
#define NB ((N_NODES + 1023) / 1024)   // 98 scan blocks

// -------- scratch (allocation-free: __device__ globals) --------
__device__ __align__(16) __half g_x16[N_NODES * IN_CH];  // fp16 copy of x
__device__ __align__(16) __half g_h1[N_NODES * IN_CH];   // fp16 intermediate
__device__ __align__(16) float  g_h2[N_NODES * IN_CH];   // fp32 (feeds GEMM)
__device__ float g_dinv[N_NODES];
__device__ int   g_deg[N_NODES];
__device__ int   g_off[N_NODES + 1];
__device__ int   g_cur[N_NODES];
__device__ int   g_src[N_EDGES];   // CSR-by-dst: source node per slot
__device__ int   g_bsum[128];      // per-block degree sums
__device__ int   g_is64;           // 1 if edge_index is int64, 0 if int32

// packed f32x2 FMA (FFMA2 — only reachable via PTX fma.rn.f32x2)
#define FMA_F32X2(d, a, b, c) \
    asm("fma.rn.f32x2 %0, %1, %2, %3;" : "=l"(d) : "l"(a), "l"(b), "l"(c))

// -------- 0. zero degree + dtype sniff + x -> fp16 conversion --------
__global__ void k_zero(const int* __restrict__ ei32,
                       const float4* __restrict__ x) {
    int i = blockIdx.x * blockDim.x + threadIdx.x;
    int stride = gridDim.x * blockDim.x;
    for (int j = i; j < N_NODES; j += stride) g_deg[j] = 0;
    uint2* x16 = reinterpret_cast<uint2*>(g_x16);
    const int n4 = N_NODES * V4_PER_ROW;
    for (int j = i; j < n4; j += stride) {
        float4 v = x[j];
        __half2 p0 = __floats2half2_rn(v.x, v.y);
        __half2 p1 = __floats2half2_rn(v.z, v.w);
        uint2 pk;
        pk.x = *reinterpret_cast<unsigned int*>(&p0);
        pk.y = *reinterpret_cast<unsigned int*>(&p1);
        x16[j] = pk;
    }
    if (i == 0) {   // int64 LE indices < 2^31 have every odd int32 word == 0
        int nz = 0;
        for (int k = 0; k < 128; k++) nz |= ei32[2 * k + 1];
        g_is64 = (nz == 0) ? 1 : 0;
    }
}

// -------- 1. degree histogram over dst (decode col half only) --------
__global__ void k_deg(const void* __restrict__ eiraw) {
    int e = blockIdx.x * blockDim.x + threadIdx.x;
    if (e >= N_EDGES) return;
    int c;
    if (g_is64) c = (int)((const long long*)eiraw)[N_EDGES + e];
    else        c = ((const int*)eiraw)[N_EDGES + e];
    c = min(max(c, 0), N_NODES - 1);
    atomicAdd(&g_deg[c], 1);
}

// -------- 2a. per-block exclusive scan (warp shuffles) + dinv --------
__global__ void k_scan1() {
    __shared__ int warp_sums[32];
    int i = blockIdx.x * 1024 + threadIdx.x;
    int v = (i < N_NODES) ? g_deg[i] : 0;
    if (i < N_NODES) g_dinv[i] = (v > 0) ? rsqrtf((float)v) : 0.0f;

    int lane = threadIdx.x & 31;
    int warp = threadIdx.x >> 5;
    int s = v;
#pragma unroll
    for (int o = 1; o < 32; o <<= 1) {
        int t = __shfl_up_sync(0xffffffffu, s, o);
        if (lane >= o) s += t;
    }
    if (lane == 31) warp_sums[warp] = s;
    __syncthreads();
    if (warp == 0) {
        int ws = warp_sums[lane];
#pragma unroll
        for (int o = 1; o < 32; o <<= 1) {
            int t = __shfl_up_sync(0xffffffffu, ws, o);
            if (lane >= o) ws += t;
        }
        warp_sums[lane] = ws;
    }
    __syncthreads();
    int excl = s - v + ((warp > 0) ? warp_sums[warp - 1] : 0);
    if (i < N_NODES) g_off[i] = excl;                        // block-local excl
    if (threadIdx.x == 1023) g_bsum[blockIdx.x] = excl + v;  // block total
}

// -------- 2b. block-sum scan (redundant per block) + offset add --------
__global__ void k_scan3() {
    __shared__ int sh[128];
    int tid = threadIdx.x;
    if (tid < 128) sh[tid] = (tid < NB) ? g_bsum[tid] : 0;
    __syncthreads();
    for (int o = 1; o < 128; o <<= 1) {
        int x = (tid >= o && tid < 128) ? sh[tid - o] : 0;
        __syncthreads();
        if (tid < 128) sh[tid] += x;
        __syncthreads();
    }
    int i = blockIdx.x * blockDim.x + tid;
    if (i < N_NODES) {
        int blk = i >> 10;
        int boff = (blk > 0) ? sh[blk - 1] : 0;
        int o = g_off[i] + boff;
        g_off[i] = o;
        g_cur[i] = o;
    }
    if (blockIdx.x == 0 && tid == 0) g_off[N_NODES] = sh[127];
}

// -------- 3. counting-sort edges by destination (src only) --------
__global__ void k_place(const void* __restrict__ eiraw) {
    int e = blockIdx.x * blockDim.x + threadIdx.x;
    if (e >= N_EDGES) return;
    int r, c;
    if (g_is64) {
        const long long* ei = (const long long*)eiraw;
        r = (int)ei[e];
        c = (int)ei[N_EDGES + e];
    } else {
        const int* ei = (const int*)eiraw;
        r = ei[e];
        c = ei[N_EDGES + e];
    }
    r = min(max(r, 0), N_NODES - 1);
    c = min(max(c, 0), N_NODES - 1);
    int pos = atomicAdd(&g_cur[c], 1);
    g_src[pos] = r;
}

// -------- 4. propagation step: dst = A src (fp16 gather, fp32 acc) --------
// STAGE 0: src = g_x16, dst = g_h1 (fp16). STAGE 1: src = g_h1, dst = g_h2 (fp32).
// Device-symbol selection happens IN DEVICE CODE (host must not touch symbols).
template <int STAGE>
__global__ void k_prop() {
    const uint2* __restrict__ src = reinterpret_cast<const uint2*>(
        STAGE == 0 ? g_x16 : g_h1);

    int t = blockIdx.x * blockDim.x + threadIdx.x;
    int node = t / V4_PER_ROW;
    int lane = t - node * V4_PER_ROW;
    if (node >= N_NODES) return;
    int beg = g_off[node];
    int end = g_off[node + 1];
    float dc = g_dinv[node];
    float4 acc = make_float4(0.f, 0.f, 0.f, 0.f);
    int k = beg;
    for (; k + 4 <= end; k += 4) {
        int s0 = g_src[k], s1 = g_src[k + 1], s2 = g_src[k + 2], s3 = g_src[k + 3];
        float w0 = g_dinv[s0] * dc, w1 = g_dinv[s1] * dc;
        float w2 = g_dinv[s2] * dc, w3 = g_dinv[s3] * dc;
        uint2 r0 = src[s0 * V4_PER_ROW + lane];
        uint2 r1 = src[s1 * V4_PER_ROW + lane];
        uint2 r2 = src[s2 * V4_PER_ROW + lane];
        uint2 r3 = src[s3 * V4_PER_ROW + lane];
        float2 a0 = __half22float2(*reinterpret_cast<__half2*>(&r0.x));
        float2 b0 = __half22float2(*reinterpret_cast<__half2*>(&r0.y));
        float2 a1 = __half22float2(*reinterpret_cast<__half2*>(&r1.x));
        float2 b1 = __half22float2(*reinterpret_cast<__half2*>(&r1.y));
        float2 a2 = __half22float2(*reinterpret_cast<__half2*>(&r2.x));
        float2 b2 = __half22float2(*reinterpret_cast<__half2*>(&r2.y));
        float2 a3 = __half22float2(*reinterpret_cast<__half2*>(&r3.x));
        float2 b3 = __half22float2(*reinterpret_cast<__half2*>(&r3.y));
        acc.x += a0.x * w0 + a1.x * w1 + a2.x * w2 + a3.x * w3;
        acc.y += a0.y * w0 + a1.y * w1 + a2.y * w2 + a3.y * w3;
        acc.z += b0.x * w0 + b1.x * w1 + b2.x * w2 + b3.x * w3;
        acc.w += b0.y * w0 + b1.y * w1 + b2.y * w2 + b3.y * w3;
    }
    for (; k < end; k++) {
        int s0 = g_src[k];
        float w0 = g_dinv[s0] * dc;
        uint2 r0 = src[s0 * V4_PER_ROW + lane];
        float2 a0 = __half22float2(*reinterpret_cast<__half2*>(&r0.x));
        float2 b0 = __half22float2(*reinterpret_cast<__half2*>(&r0.y));
        acc.x += a0.x * w0;
        acc.y += a0.y * w0;
        acc.z += b0.x * w0;
        acc.w += b0.y * w0;
    }
    if (STAGE == 0) {
        __half2 p0 = __floats2half2_rn(acc.x, acc.y);
        __half2 p1 = __floats2half2_rn(acc.z, acc.w);
        uint2 pk;
        pk.x = *reinterpret_cast<unsigned int*>(&p0);
        pk.y = *reinterpret_cast<unsigned int*>(&p1);
        reinterpret_cast<uint2*>(g_h1)[node * V4_PER_ROW + lane] = pk;
    } else {
        reinterpret_cast<float4*>(g_h2)[node * V4_PER_ROW + lane] = acc;
    }
}

// -------- 5. dense epilogue: out = g_h2 @ W + b (packed f32x2 FMA) --------
__global__ void k_gemm(const float* __restrict__ W,
                       const float* __restrict__ b,
                       float* __restrict__ out) {
    __shared__ __align__(16) float Ws[IN_CH * OUT_CH];
    __shared__ __align__(16) float bs[OUT_CH];
    for (int i = threadIdx.x; i < IN_CH * OUT_CH; i += blockDim.x) Ws[i] = W[i];
    if (threadIdx.x < OUT_CH) bs[threadIdx.x] = b[threadIdx.x];
    __syncthreads();

    int n = blockIdx.x * blockDim.x + threadIdx.x;
    if (n >= N_NODES) return;

    unsigned long long acc[OUT_CH / 2];
    const unsigned long long* bs2 = reinterpret_cast<const unsigned long long*>(bs);
#pragma unroll
    for (int j = 0; j < OUT_CH / 2; j++) acc[j] = bs2[j];

    const float4* hr = reinterpret_cast<const float4*>(g_h2 + (long long)n * IN_CH);
#pragma unroll
    for (int k4 = 0; k4 < V4_PER_ROW; k4++) {
        float4 xv = hr[k4];
        unsigned long long ax, ay, az, aw;
        unsigned int bx = __float_as_uint(xv.x), by = __float_as_uint(xv.y);
        unsigned int bz = __float_as_uint(xv.z), bw = __float_as_uint(xv.w);
        asm("mov.b64 %0, {%1, %1};" : "=l"(ax) : "r"(bx));
        asm("mov.b64 %0, {%1, %1};" : "=l"(ay) : "r"(by));
        asm("mov.b64 %0, {%1, %1};" : "=l"(az) : "r"(bz));
        asm("mov.b64 %0, {%1, %1};" : "=l"(aw) : "r"(bw));
        const unsigned long long* w0 =
            reinterpret_cast<const unsigned long long*>(&Ws[(k4 * 4 + 0) * OUT_CH]);
        const unsigned long long* w1 =
            reinterpret_cast<const unsigned long long*>(&Ws[(k4 * 4 + 1) * OUT_CH]);
        const unsigned long long* w2 =
            reinterpret_cast<const unsigned long long*>(&Ws[(k4 * 4 + 2) * OUT_CH]);
        const unsigned long long* w3 =
            reinterpret_cast<const unsigned long long*>(&Ws[(k4 * 4 + 3) * OUT_CH]);
#pragma unroll
        for (int j = 0; j < OUT_CH / 2; j++) {
            FMA_F32X2(acc[j], ax, w0[j], acc[j]);
            FMA_F32X2(acc[j], ay, w1[j], acc[j]);
            FMA_F32X2(acc[j], az, w2[j], acc[j]);
            FMA_F32X2(acc[j], aw, w3[j], acc[j]);
        }
    }

    uint4* o = reinterpret_cast<uint4*>(out + (long long)n * OUT_CH);
#pragma unroll
    for (int j = 0; j < OUT_CH / 4; j++) {
        unsigned int p, q, r, s;
        asm("mov.b64 {%0, %1}, %2;" : "=r"(p), "=r"(q) : "l"(acc[2 * j]));
        asm("mov.b64 {%0, %1}, %2;" : "=r"(r), "=r"(s) : "l"(acc[2 * j + 1]));
        uint4 v; v.x = p; v.y = q; v.z = r; v.w = s;
        o[j] = v;
    }
}

extern "C" void kernel_launch(void* const* d_in, const int* in_sizes, int n_in,
                              void* d_out, int out_size) {
    const float* x  = (const float*)d_in[0];   // [N_NODES, IN_CH]
    const void*  ei = d_in[1];                 // [2, N_EDGES] int32 OR int64
    const float* W  = (const float*)d_in[2];   // [IN_CH, OUT_CH]
    const float* b  = (const float*)d_in[3];   // [OUT_CH]
    float*       out = (float*)d_out;          // [N_NODES, OUT_CH]

    // CSR build + x fp16 conversion
    const int n4 = N_NODES * V4_PER_ROW;
    k_zero<<<(n4 + 255) / 256, 256>>>((const int*)ei, (const float4*)x);
    k_deg<<<(N_EDGES + 255) / 256, 256>>>(ei);
    k_scan1<<<NB, 1024>>>();
    k_scan3<<<(N_NODES + 255) / 256, 256>>>();
    k_place<<<(N_EDGES + 255) / 256, 256>>>(ei);

    // two propagation steps: h1 = A x16 ; h2 = A h1
    const int threads = 192;                 // 16 nodes per block * 12 lanes
    const int total = N_NODES * V4_PER_ROW;
    int grid = (total + threads - 1) / threads;
    k_prop<0><<<grid, threads>>>();
    k_prop<1><<<grid, threads>>>();

    // out = h2 @ W + b
    k_gemm<<<(N_NODES + 127) / 128, 128>>>(W, b, out);
}

// round 10
// speedup vs baseline: 2.2398x; 1.0287x over previous
#include <cuda_runtime.h>
#include <cuda_fp16.h>
#include <cuda_bf16.h>

#define N_NODES 100000
#define N_EDGES 1600000
#define IN_CH   48
#define OUT_CH  64
#define V8_PER_ROW (IN_CH / 8)   // 6 chunks of 8 fp16 channels (16B) per row
#define NB ((N_NODES + 1023) / 1024)   // 98 scan blocks

// -------- scratch (allocation-free: __device__ globals) --------
// INVARIANT: g_deg == 0 at kernel_launch entry. CUDA zero-inits device
// globals; k_scan1 re-zeroes after consuming, so the invariant holds on
// every call (correctness run, capture, every replay).
__device__ __align__(16) __half g_x16[N_NODES * IN_CH];  // fp16 copy of x
__device__ __align__(16) __half g_h1[N_NODES * IN_CH];   // fp16 intermediate
__device__ __align__(16) float  g_h2[N_NODES * IN_CH];   // fp32 (feeds GEMM)
__device__ float g_dinv[N_NODES];
__device__ int   g_deg[N_NODES];
__device__ int   g_off[N_NODES + 1];
__device__ int   g_cur[N_NODES];
__device__ int   g_src[N_EDGES];   // CSR-by-dst: source node per slot
__device__ int   g_bsum[128];      // per-block degree sums
__device__ int   g_is64;           // 1 if edge_index is int64, 0 if int32

// packed f32x2 FMA (FFMA2 — only reachable via PTX fma.rn.f32x2)
#define FMA_F32X2(d, a, b, c) \
    asm("fma.rn.f32x2 %0, %1, %2, %3;" : "=l"(d) : "l"(a), "l"(b), "l"(c))

// -------- 1. fused: dtype sniff + degree histogram + x -> fp16 --------
__global__ void k_build(const int* __restrict__ ei32,
                        const float4* __restrict__ x) {
    __shared__ int s_is64;
    if (threadIdx.x == 0) {
        // int64 LE indices < 2^31 have every odd int32 word == 0
        int nz = 0;
#pragma unroll
        for (int k = 0; k < 128; k++) nz |= ei32[2 * k + 1];
        s_is64 = (nz == 0) ? 1 : 0;
        if (blockIdx.x == 0) g_is64 = s_is64;
    }
    __syncthreads();
    const int is64 = s_is64;

    int i = blockIdx.x * blockDim.x + threadIdx.x;
    int stride = gridDim.x * blockDim.x;

    // degree histogram over destination (col) indices
    for (int e = i; e < N_EDGES; e += stride) {
        int c = is64 ? (int)((const long long*)ei32)[N_EDGES + e]
                     : ei32[N_EDGES + e];
        c = min(max(c, 0), N_NODES - 1);
        atomicAdd(&g_deg[c], 1);
    }

    // x -> fp16 streaming conversion
    uint2* x16 = reinterpret_cast<uint2*>(g_x16);
    const int n4 = N_NODES * IN_CH / 4;
    for (int j = i; j < n4; j += stride) {
        float4 v = x[j];
        __half2 p0 = __floats2half2_rn(v.x, v.y);
        __half2 p1 = __floats2half2_rn(v.z, v.w);
        uint2 pk;
        pk.x = *reinterpret_cast<unsigned int*>(&p0);
        pk.y = *reinterpret_cast<unsigned int*>(&p1);
        x16[j] = pk;
    }
}

// -------- 2a. per-block exclusive scan + dinv + deg cleanup --------
__global__ void k_scan1() {
    __shared__ int warp_sums[32];
    int i = blockIdx.x * 1024 + threadIdx.x;
    int v = (i < N_NODES) ? g_deg[i] : 0;
    if (i < N_NODES) {
        g_dinv[i] = (v > 0) ? rsqrtf((float)v) : 0.0f;
        g_deg[i] = 0;   // restore invariant for the next replay
    }

    int lane = threadIdx.x & 31;
    int warp = threadIdx.x >> 5;
    int s = v;
#pragma unroll
    for (int o = 1; o < 32; o <<= 1) {
        int t = __shfl_up_sync(0xffffffffu, s, o);
        if (lane >= o) s += t;
    }
    if (lane == 31) warp_sums[warp] = s;
    __syncthreads();
    if (warp == 0) {
        int ws = warp_sums[lane];
#pragma unroll
        for (int o = 1; o < 32; o <<= 1) {
            int t = __shfl_up_sync(0xffffffffu, ws, o);
            if (lane >= o) ws += t;
        }
        warp_sums[lane] = ws;
    }
    __syncthreads();
    int excl = s - v + ((warp > 0) ? warp_sums[warp - 1] : 0);
    if (i < N_NODES) g_off[i] = excl;                        // block-local excl
    if (threadIdx.x == 1023) g_bsum[blockIdx.x] = excl + v;  // block total
}

// -------- 2b. block-sum scan (redundant per block) + offset add --------
__global__ void k_scan3() {
    __shared__ int sh[128];
    int tid = threadIdx.x;
    if (tid < 128) sh[tid] = (tid < NB) ? g_bsum[tid] : 0;
    __syncthreads();
    for (int o = 1; o < 128; o <<= 1) {
        int x = (tid >= o && tid < 128) ? sh[tid - o] : 0;
        __syncthreads();
        if (tid < 128) sh[tid] += x;
        __syncthreads();
    }
    int i = blockIdx.x * blockDim.x + tid;
    if (i < N_NODES) {
        int blk = i >> 10;
        int boff = (blk > 0) ? sh[blk - 1] : 0;
        int o = g_off[i] + boff;
        g_off[i] = o;
        g_cur[i] = o;
    }
    if (blockIdx.x == 0 && tid == 0) g_off[N_NODES] = sh[127];
}

// -------- 3. counting-sort edges by destination (src only) --------
__global__ void k_place(const void* __restrict__ eiraw) {
    int e = blockIdx.x * blockDim.x + threadIdx.x;
    if (e >= N_EDGES) return;
    int r, c;
    if (g_is64) {
        const long long* ei = (const long long*)eiraw;
        r = (int)ei[e];
        c = (int)ei[N_EDGES + e];
    } else {
        const int* ei = (const int*)eiraw;
        r = ei[e];
        c = ei[N_EDGES + e];
    }
    r = min(max(r, 0), N_NODES - 1);
    c = min(max(c, 0), N_NODES - 1);
    int pos = atomicAdd(&g_cur[c], 1);
    g_src[pos] = r;
}

// -------- 4. propagation: 6 lanes/node, 16B fp16 gathers, fp32 acc --------
// STAGE 0: src = g_x16 -> g_h1 (fp16). STAGE 1: src = g_h1 -> g_h2 (fp32).
template <int STAGE>
__global__ void k_prop() {
    const uint4* __restrict__ src = reinterpret_cast<const uint4*>(
        STAGE == 0 ? g_x16 : g_h1);

    int t = blockIdx.x * blockDim.x + threadIdx.x;
    int node = t / V8_PER_ROW;
    int lane = t - node * V8_PER_ROW;
    if (node >= N_NODES) return;
    int beg = g_off[node];
    int end = g_off[node + 1];
    float dc = g_dinv[node];

    float acc[8];
#pragma unroll
    for (int j = 0; j < 8; j++) acc[j] = 0.f;

#define ACCUM_EDGE(rv, wv)                                                   \
    do {                                                                     \
        float2 f0 = __half22float2(*reinterpret_cast<__half2*>(&(rv).x));    \
        float2 f1 = __half22float2(*reinterpret_cast<__half2*>(&(rv).y));    \
        float2 f2 = __half22float2(*reinterpret_cast<__half2*>(&(rv).z));    \
        float2 f3 = __half22float2(*reinterpret_cast<__half2*>(&(rv).w));    \
        acc[0] += f0.x * (wv); acc[1] += f0.y * (wv);                        \
        acc[2] += f1.x * (wv); acc[3] += f1.y * (wv);                        \
        acc[4] += f2.x * (wv); acc[5] += f2.y * (wv);                        \
        acc[6] += f3.x * (wv); acc[7] += f3.y * (wv);                        \
    } while (0)

    int k = beg;
    for (; k + 4 <= end; k += 4) {
        int s0 = g_src[k], s1 = g_src[k + 1], s2 = g_src[k + 2], s3 = g_src[k + 3];
        float w0 = g_dinv[s0] * dc, w1 = g_dinv[s1] * dc;
        float w2 = g_dinv[s2] * dc, w3 = g_dinv[s3] * dc;
        uint4 r0 = src[s0 * V8_PER_ROW + lane];
        uint4 r1 = src[s1 * V8_PER_ROW + lane];
        uint4 r2 = src[s2 * V8_PER_ROW + lane];
        uint4 r3 = src[s3 * V8_PER_ROW + lane];
        ACCUM_EDGE(r0, w0);
        ACCUM_EDGE(r1, w1);
        ACCUM_EDGE(r2, w2);
        ACCUM_EDGE(r3, w3);
    }
    for (; k < end; k++) {
        int s0 = g_src[k];
        float w0 = g_dinv[s0] * dc;
        uint4 r0 = src[s0 * V8_PER_ROW + lane];
        ACCUM_EDGE(r0, w0);
    }
#undef ACCUM_EDGE

    if (STAGE == 0) {
        __half2 p0 = __floats2half2_rn(acc[0], acc[1]);
        __half2 p1 = __floats2half2_rn(acc[2], acc[3]);
        __half2 p2 = __floats2half2_rn(acc[4], acc[5]);
        __half2 p3 = __floats2half2_rn(acc[6], acc[7]);
        uint4 pk;
        pk.x = *reinterpret_cast<unsigned int*>(&p0);
        pk.y = *reinterpret_cast<unsigned int*>(&p1);
        pk.z = *reinterpret_cast<unsigned int*>(&p2);
        pk.w = *reinterpret_cast<unsigned int*>(&p3);
        reinterpret_cast<uint4*>(g_h1)[node * V8_PER_ROW + lane] = pk;
    } else {
        float4* drow = reinterpret_cast<float4*>(g_h2 + node * IN_CH + lane * 8);
        drow[0] = make_float4(acc[0], acc[1], acc[2], acc[3]);
        drow[1] = make_float4(acc[4], acc[5], acc[6], acc[7]);
    }
}

// -------- 5. dense epilogue: out = g_h2 @ W + b (packed f32x2 FMA) --------
__global__ void k_gemm(const float* __restrict__ W,
                       const float* __restrict__ b,
                       float* __restrict__ out) {
    __shared__ __align__(16) float Ws[IN_CH * OUT_CH];
    __shared__ __align__(16) float bs[OUT_CH];
    for (int i = threadIdx.x; i < IN_CH * OUT_CH; i += blockDim.x) Ws[i] = W[i];
    if (threadIdx.x < OUT_CH) bs[threadIdx.x] = b[threadIdx.x];
    __syncthreads();

    int n = blockIdx.x * blockDim.x + threadIdx.x;
    if (n >= N_NODES) return;

    unsigned long long acc[OUT_CH / 2];
    const unsigned long long* bs2 = reinterpret_cast<const unsigned long long*>(bs);
#pragma unroll
    for (int j = 0; j < OUT_CH / 2; j++) acc[j] = bs2[j];

    const float4* hr = reinterpret_cast<const float4*>(g_h2 + (long long)n * IN_CH);
#pragma unroll
    for (int k4 = 0; k4 < IN_CH / 4; k4++) {
        float4 xv = hr[k4];
        unsigned long long ax, ay, az, aw;
        unsigned int bx = __float_as_uint(xv.x), by = __float_as_uint(xv.y);
        unsigned int bz = __float_as_uint(xv.z), bw = __float_as_uint(xv.w);
        asm("mov.b64 %0, {%1, %1};" : "=l"(ax) : "r"(bx));
        asm("mov.b64 %0, {%1, %1};" : "=l"(ay) : "r"(by));
        asm("mov.b64 %0, {%1, %1};" : "=l"(az) : "r"(bz));
        asm("mov.b64 %0, {%1, %1};" : "=l"(aw) : "r"(bw));
        const unsigned long long* w0 =
            reinterpret_cast<const unsigned long long*>(&Ws[(k4 * 4 + 0) * OUT_CH]);
        const unsigned long long* w1 =
            reinterpret_cast<const unsigned long long*>(&Ws[(k4 * 4 + 1) * OUT_CH]);
        const unsigned long long* w2 =
            reinterpret_cast<const unsigned long long*>(&Ws[(k4 * 4 + 2) * OUT_CH]);
        const unsigned long long* w3 =
            reinterpret_cast<const unsigned long long*>(&Ws[(k4 * 4 + 3) * OUT_CH]);
#pragma unroll
        for (int j = 0; j < OUT_CH / 2; j++) {
            FMA_F32X2(acc[j], ax, w0[j], acc[j]);
            FMA_F32X2(acc[j], ay, w1[j], acc[j]);
            FMA_F32X2(acc[j], az, w2[j], acc[j]);
            FMA_F32X2(acc[j], aw, w3[j], acc[j]);
        }
    }

    uint4* o = reinterpret_cast<uint4*>(out + (long long)n * OUT_CH);
#pragma unroll
    for (int j = 0; j < OUT_CH / 4; j++) {
        unsigned int p, q, r, s;
        asm("mov.b64 {%0, %1}, %2;" : "=r"(p), "=r"(q) : "l"(acc[2 * j]));
        asm("mov.b64 {%0, %1}, %2;" : "=r"(r), "=r"(s) : "l"(acc[2 * j + 1]));
        uint4 v; v.x = p; v.y = q; v.z = r; v.w = s;
        o[j] = v;
    }
}

extern "C" void kernel_launch(void* const* d_in, const int* in_sizes, int n_in,
                              void* d_out, int out_size) {
    const float* x  = (const float*)d_in[0];   // [N_NODES, IN_CH]
    const void*  ei = d_in[1];                 // [2, N_EDGES] int32 OR int64
    const float* W  = (const float*)d_in[2];   // [IN_CH, OUT_CH]
    const float* b  = (const float*)d_in[3];   // [OUT_CH]
    float*       out = (float*)d_out;          // [N_NODES, OUT_CH]

    // CSR build (6 launches total for the whole pipeline)
    k_build<<<(N_EDGES + 511) / 512, 512>>>((const int*)ei, (const float4*)x);
    k_scan1<<<NB, 1024>>>();
    k_scan3<<<(N_NODES + 255) / 256, 256>>>();
    k_place<<<(N_EDGES + 511) / 512, 512>>>(ei);

    // two propagation steps: h1 = A x16 ; h2 = A h1
    const int threads = 192;                 // 32 nodes per block * 6 lanes
    const int total = N_NODES * V8_PER_ROW;
    int grid = (total + threads - 1) / threads;
    k_prop<0><<<grid, threads>>>();
    k_prop<1><<<grid, threads>>>();

    // out = h2 @ W + b
    k_gemm<<<(N_NODES + 127) / 128, 128>>>(W, b, out);
}